// round 8
// baseline (speedup 1.0000x reference)
#include <cuda_runtime.h>
#include <math.h>
#include <stdint.h>

#define N_NODES 16384
#define N_EDGES 524288
#define ET (N_EDGES + N_NODES)      // edges + self loops
#define HEADS 3
#define HID 64
#define IN_DIM 128
#define FEAT (HEADS * HID)          // 192
#define G4 (4 * HID)                // 256
#define NEG_SLOPE 0.2f
#define NODE_MASK (N_NODES - 1)     // N_NODES is 2^14

// ---------------- scratch (static device allocations; no cudaMalloc) ----------
__device__ float d_h[(size_t)N_NODES * FEAT];       // GAT transformed features
__device__ float d_asrc[N_NODES * HEADS];
__device__ float d_adst[N_NODES * HEADS];
__device__ float d_z[N_NODES * HEADS];              // softmax denominators
__device__ float d_p[(size_t)ET * HEADS];           // per-edge exp(e)
__device__ float d_gacc[(size_t)N_NODES * HID];     // aggregated messages (mean over heads)
__device__ float d_xg[(size_t)N_NODES * G4];        // precomputed input gates for LSTM
__device__ float d_hn[(size_t)N_NODES * HID];       // row-normalized h
__device__ int   d_is64;                            // edge_index dtype flag

// ---------------- edge dtype detection (int32 vs int64) -----------------------
__global__ void k_detect(const int* __restrict__ ei) {
    int is64 = 1;
#pragma unroll
    for (int k = 0; k < 8; k++)
        if (ei[2 * k + 1] != 0) is64 = 0;
    d_is64 = is64;
}

__device__ __forceinline__ void load_edge(const int* __restrict__ ei, int e, int is64,
                                          int& s, int& d) {
    if (e < N_EDGES) {
        if (is64) {
            const long long* e64 = (const long long*)ei;
            s = (int)e64[e];
            d = (int)e64[N_EDGES + e];
        } else {
            s = ei[e];
            d = ei[N_EDGES + e];
        }
        s &= NODE_MASK;
        d &= NODE_MASK;
    } else {
        s = d = e - N_EDGES;
    }
}

// ---------------- init: zero the accumulators (must run every replay) ---------
__global__ void k_init() {
    for (int i = blockIdx.x * blockDim.x + threadIdx.x;
         i < N_NODES * HID; i += gridDim.x * blockDim.x) {
        if (i < N_NODES * HEADS) d_z[i] = 0.f;
        d_gacc[i] = 0.f;
    }
}

// ---------------- generic 64x64-tile NT GEMM: C = (A + abias) * B^T + cb1 + cb2
__device__ __forceinline__ void gemm_body(
    const float* __restrict__ A, int K,
    const float* __restrict__ B,
    float* __restrict__ C, int M,
    const float* __restrict__ abias,
    const float* __restrict__ cb1,
    const float* __restrict__ cb2)
{
    __shared__ float As[64][65];
    __shared__ float Bs[64][65];
    int tid = threadIdx.x;
    int tx = tid & 15;
    int ty = tid >> 4;
    int n0 = blockIdx.y * 64;
    int m0 = blockIdx.x * 64;

    float acc[4][4];
#pragma unroll
    for (int i = 0; i < 4; i++)
#pragma unroll
        for (int j = 0; j < 4; j++) acc[i][j] = 0.f;

    for (int k0 = 0; k0 < K; k0 += 64) {
#pragma unroll
        for (int i = 0; i < 16; i++) {
            int idx = tid + i * 256;
            int r = idx >> 6;
            int k = idx & 63;
            float av = A[(size_t)(n0 + r) * K + k0 + k];
            if (abias) av += abias[k0 + k];
            As[r][k] = av;
            Bs[r][k] = B[(size_t)(m0 + r) * K + k0 + k];
        }
        __syncthreads();
#pragma unroll
        for (int k = 0; k < 64; k++) {
            float a[4], b[4];
#pragma unroll
            for (int i = 0; i < 4; i++) {
                a[i] = As[ty * 4 + i][k];
                b[i] = Bs[tx * 4 + i][k];
            }
#pragma unroll
            for (int i = 0; i < 4; i++)
#pragma unroll
                for (int j = 0; j < 4; j++)
                    acc[i][j] = fmaf(a[i], b[j], acc[i][j]);
        }
        __syncthreads();
    }

#pragma unroll
    for (int i = 0; i < 4; i++)
#pragma unroll
        for (int j = 0; j < 4; j++) {
            int m = m0 + tx * 4 + j;
            float v = acc[i][j];
            if (cb1) v += cb1[m];
            if (cb2) v += cb2[m];
            C[(size_t)(n0 + ty * 4 + i) * M + m] = v;
        }
}

__global__ void k_gemm_h(const float* __restrict__ x, const float* __restrict__ lin_w) {
    gemm_body(x, IN_DIM, lin_w, d_h, FEAT, nullptr, nullptr, nullptr);
}

__global__ void k_gemm_xg(const float* __restrict__ w_ih, const float* __restrict__ gat_bias,
                          const float* __restrict__ b_ih, const float* __restrict__ b_hh) {
    gemm_body(d_gacc, HID, w_ih, d_xg, G4, gat_bias, b_ih, b_hh);
}

// ---------------- corr: symmetric NT GEMM, k-major smem, float4 LDS -----------
// C = hn @ hn^T, tiles bx >= by only; mirror tile written via transposed staging.
__global__ void k_corr_sym(float* __restrict__ C) {
    int bx = blockIdx.x, by = blockIdx.y;
    if (bx < by) return;

    __shared__ __align__(16) float As[64][68];   // [k][row], 272B rows (16B aligned)
    __shared__ __align__(16) float Bs[64][68];   // [k][col]
    int tid = threadIdx.x;
    int tx = tid & 15;
    int ty = tid >> 4;
    int n0 = by * 64;        // row tile
    int m0 = bx * 64;        // col tile
    const float* A = d_hn;

    float acc[4][4];
#pragma unroll
    for (int i = 0; i < 4; i++)
#pragma unroll
        for (int j = 0; j < 4; j++) acc[i][j] = 0.f;

    // load K=64 tile, k-major (transposed) layout
#pragma unroll
    for (int i = 0; i < 16; i++) {
        int idx = tid + i * 256;
        int r = idx >> 6;        // row/col within tile
        int k = idx & 63;        // k index (fastest-varying -> coalesced LDG)
        As[k][r] = A[(size_t)(n0 + r) * HID + k];
        Bs[k][r] = A[(size_t)(m0 + r) * HID + k];
    }
    __syncthreads();
#pragma unroll
    for (int k = 0; k < 64; k++) {
        float4 a4 = *(const float4*)&As[k][ty * 4];
        float4 b4 = *(const float4*)&Bs[k][tx * 4];
        float a[4] = {a4.x, a4.y, a4.z, a4.w};
        float b[4] = {b4.x, b4.y, b4.z, b4.w};
#pragma unroll
        for (int i = 0; i < 4; i++)
#pragma unroll
            for (int j = 0; j < 4; j++)
                acc[i][j] = fmaf(a[i], b[j], acc[i][j]);
    }

    // direct tile write: C[n0+r][m0+c]
#pragma unroll
    for (int i = 0; i < 4; i++)
#pragma unroll
        for (int j = 0; j < 4; j++)
            C[(size_t)(n0 + ty * 4 + i) * N_NODES + m0 + tx * 4 + j] = acc[i][j];

    if (bx == by) return;

    // mirror: stage transposed (S[a][b] = tile[b][a]), then coalesced write.
    __syncthreads();
#pragma unroll
    for (int i = 0; i < 4; i++)
#pragma unroll
        for (int j = 0; j < 4; j++)
            As[tx * 4 + j][ty * 4 + i] = acc[i][j];
    __syncthreads();
    int col = tid & 63;
    int r0 = tid >> 6;
#pragma unroll
    for (int i = 0; i < 16; i++) {
        int row = i * 4 + r0;
        // C[m0+row][n0+col] = tile[col][row] = As[row][col]
        C[(size_t)(m0 + row) * N_NODES + n0 + col] = As[row][col];
    }
}

// ---------------- attention coefficients a_src, a_dst (warp per node) ---------
__global__ void k_attn(const float* __restrict__ att_src, const float* __restrict__ att_dst) {
    int warp = threadIdx.x >> 5;
    int lane = threadIdx.x & 31;
    int n = blockIdx.x * 8 + warp;
    if (n >= N_NODES) return;
    const float* hr = d_h + (size_t)n * FEAT;
#pragma unroll
    for (int hd = 0; hd < HEADS; hd++) {
        float h0 = hr[hd * 64 + lane];
        float h1 = hr[hd * 64 + 32 + lane];
        float s1 = h0 * att_src[hd * 64 + lane] + h1 * att_src[hd * 64 + 32 + lane];
        float s2 = h0 * att_dst[hd * 64 + lane] + h1 * att_dst[hd * 64 + 32 + lane];
#pragma unroll
        for (int o = 16; o; o >>= 1) {
            s1 += __shfl_xor_sync(0xffffffffu, s1, o);
            s2 += __shfl_xor_sync(0xffffffffu, s2, o);
        }
        if (lane == 0) {
            d_asrc[n * 3 + hd] = s1;
            d_adst[n * 3 + hd] = s2;
        }
    }
}

// ---------------- edge pass 1: p = exp(leakyrelu(e)), z accumulation ----------
__global__ void k_edge_z(const int* __restrict__ ei) {
    int e = blockIdx.x * blockDim.x + threadIdx.x;
    if (e >= ET) return;
    int is64 = d_is64;
    int s, d;
    load_edge(ei, e, is64, s, d);
#pragma unroll
    for (int hd = 0; hd < 3; hd++) {
        float ev = d_asrc[s * 3 + hd] + d_adst[d * 3 + hd];
        ev = ev > 0.f ? ev : NEG_SLOPE * ev;
        float p = __expf(ev);
        d_p[(size_t)e * 3 + hd] = p;
        atomicAdd(&d_z[d * 3 + hd], p);
    }
}

// ---------------- edge pass 2: scatter messages (64 threads per edge) ---------
__global__ void k_edge_msg(const int* __restrict__ ei) {
    int le = threadIdx.x >> 6;
    int c = threadIdx.x & 63;
    int e = blockIdx.x * 4 + le;
    if (e >= ET) return;
    int is64 = d_is64;
    int s, d;
    load_edge(ei, e, is64, s, d);
    float a0 = d_p[(size_t)e * 3 + 0] / d_z[d * 3 + 0];
    float a1 = d_p[(size_t)e * 3 + 1] / d_z[d * 3 + 1];
    float a2 = d_p[(size_t)e * 3 + 2] / d_z[d * 3 + 2];
    const float* hr = d_h + (size_t)s * FEAT;
    float msg = (hr[c] * a0 + hr[64 + c] * a1 + hr[128 + c] * a2) * (1.f / 3.f);
    atomicAdd(&d_gacc[(size_t)d * 64 + c], msg);
}

// ---------------- LSTM: 128 threads, role-paired, ONE barrier/step ------------
// Thread t: unit u=t>>1, role r=t&1.
//   r=0 computes gate rows u (i) and 128+u (g); sends i*g via shfl.
//   r=1 computes gate rows 64+u (f) and 192+u (o); owns c, writes h.
// Ping-pong h buffers make a single __syncthreads per step sufficient.
__global__ void __launch_bounds__(128, 1) k_lstm(const float* __restrict__ w_hh,
                                                 float* __restrict__ out_h) {
    __shared__ __align__(16) float h_s[2][64];
    int t = threadIdx.x;
    int u = t >> 1;
    int r = t & 1;
    int rowA = u + (r << 6);          // i (r=0) / f (r=1)
    int rowB = 128 + u + (r << 6);    // g (r=0) / o (r=1)

    // packed weights: wX[j] = (w[2j], w[2j+1]) of the row
    unsigned long long wA[32], wB[32];
    {
        const float* wa = w_hh + (size_t)rowA * 64;
        const float* wb = w_hh + (size_t)rowB * 64;
#pragma unroll
        for (int k = 0; k < 32; k++) {
            asm("mov.b64 %0, {%1, %2};" : "=l"(wA[k]) : "f"(wa[2 * k]), "f"(wa[2 * k + 1]));
            asm("mov.b64 %0, {%1, %2};" : "=l"(wB[k]) : "f"(wb[2 * k]), "f"(wb[2 * k + 1]));
        }
    }

    float c = 0.f;
    if (t < 64) h_s[0][t] = 0.f;
    __syncthreads();

    // xg prefetch rings, depth 3
    float xa0 = __ldg(&d_xg[rowA]);
    float xb0 = __ldg(&d_xg[rowB]);
    float xa1 = __ldg(&d_xg[G4 + rowA]);
    float xb1 = __ldg(&d_xg[G4 + rowB]);
    float xa2 = __ldg(&d_xg[2 * G4 + rowA]);
    float xb2 = __ldg(&d_xg[2 * G4 + rowB]);

    for (int step = 0; step < N_NODES; step++) {
        int cur = step & 1;
        float xa3 = 0.f, xb3 = 0.f;
        if (step + 3 < N_NODES) {
            xa3 = __ldg(&d_xg[(size_t)(step + 3) * G4 + rowA]);
            xb3 = __ldg(&d_xg[(size_t)(step + 3) * G4 + rowB]);
        }

        unsigned long long a0 = 0ull, a1 = 0ull, b0 = 0ull, b1 = 0ull;
        const ulonglong2* h2 = (const ulonglong2*)h_s[cur];
#pragma unroll
        for (int k = 0; k < 16; k++) {
            ulonglong2 hv = h2[k];  // h[4k..4k+3] as two packed f32x2
            asm("fma.rn.f32x2 %0, %1, %2, %0;" : "+l"(a0) : "l"(wA[2 * k]),     "l"(hv.x));
            asm("fma.rn.f32x2 %0, %1, %2, %0;" : "+l"(a1) : "l"(wA[2 * k + 1]), "l"(hv.y));
            asm("fma.rn.f32x2 %0, %1, %2, %0;" : "+l"(b0) : "l"(wB[2 * k]),     "l"(hv.x));
            asm("fma.rn.f32x2 %0, %1, %2, %0;" : "+l"(b1) : "l"(wB[2 * k + 1]), "l"(hv.y));
        }
        asm("add.rn.f32x2 %0, %0, %1;" : "+l"(a0) : "l"(a1));
        asm("add.rn.f32x2 %0, %0, %1;" : "+l"(b0) : "l"(b1));
        float aLo, aHi, bLo, bHi;
        asm("mov.b64 {%0, %1}, %2;" : "=f"(aLo), "=f"(aHi) : "l"(a0));
        asm("mov.b64 {%0, %1}, %2;" : "=f"(bLo), "=f"(bHi) : "l"(b0));
        float gA = xa0 + (aLo + aHi);
        float gB = xb0 + (bLo + bHi);

        // rowA is always sigmoid (i or f). rowB: tanh for r=0 (g), sigmoid for r=1 (o).
        float sigA = 1.f / (1.f + __expf(-gA));
        float eB2 = __expf(2.f * gB);
        float tanhB = 1.f - 2.f / (eB2 + 1.f);
        float sigB = 1.f / (1.f + __expf(-gB));
        float actB = (r == 0) ? tanhB : sigB;

        float v = sigA * actB;                      // r=0: i*g (sent); r=1: unused
        float ig = __shfl_xor_sync(0xffffffffu, v, 1);

        if (r == 1) {
            c = fmaf(sigA, c, ig);                  // c = f*c + i*g
            float e2 = __expf(2.f * c);
            float th = 1.f - 2.f / (e2 + 1.f);      // tanh(c)
            float hv = actB * th;                   // h = o * tanh(c)
            h_s[cur ^ 1][u] = hv;
            out_h[(size_t)step * HID + u] = hv;
        }
        __syncthreads();

        xa0 = xa1; xa1 = xa2; xa2 = xa3;
        xb0 = xb1; xb1 = xb2; xb2 = xb3;
    }
}

// ---------------- row normalization ------------------------------------------
__global__ void k_norm(const float* __restrict__ out_h) {
    int warp = threadIdx.x >> 5;
    int lane = threadIdx.x & 31;
    int n = blockIdx.x * 8 + warp;
    if (n >= N_NODES) return;
    float v0 = out_h[(size_t)n * 64 + lane];
    float v1 = out_h[(size_t)n * 64 + 32 + lane];
    float ss = v0 * v0 + v1 * v1;
#pragma unroll
    for (int o = 16; o; o >>= 1) ss += __shfl_xor_sync(0xffffffffu, ss, o);
    float nrm = fmaxf(sqrtf(ss), 1e-12f);
    float inv = 1.f / nrm;
    d_hn[(size_t)n * 64 + lane] = v0 * inv;
    d_hn[(size_t)n * 64 + 32 + lane] = v1 * inv;
}

// ---------------- uncertainty MLP heads (warp per node) -----------------------
__global__ void k_mlp(const float* __restrict__ out_h,
                      const float* __restrict__ w1, const float* __restrict__ b1,
                      const float* __restrict__ w2, const float* __restrict__ b2,
                      float* __restrict__ mu, float* __restrict__ sigma) {
    int warp = threadIdx.x >> 5;
    int lane = threadIdx.x & 31;
    int n = blockIdx.x * 8 + warp;
    if (n >= N_NODES) return;
    const float* hr = out_h + (size_t)n * 64;
    float acc = b1[lane];
#pragma unroll
    for (int k = 0; k < 64; k++) acc = fmaf(hr[k], w1[lane * 64 + k], acc);
    acc = fmaxf(acc, 0.f);
    float m0 = acc * w2[lane];
    float m1 = acc * w2[32 + lane];
#pragma unroll
    for (int o = 16; o; o >>= 1) {
        m0 += __shfl_xor_sync(0xffffffffu, m0, o);
        m1 += __shfl_xor_sync(0xffffffffu, m1, o);
    }
    if (lane == 0) {
        mu[n] = m0 + b2[0];
        sigma[n] = m1 + b2[1];
    }
}

// ---------------- launcher ----------------------------------------------------
extern "C" void kernel_launch(void* const* d_in, const int* in_sizes, int n_in,
                              void* d_out, int out_size) {
    const float* x        = (const float*)d_in[0];
    const int*   ei       = (const int*)d_in[1];
    const float* lin_w    = (const float*)d_in[2];
    const float* att_src  = (const float*)d_in[3];
    const float* att_dst  = (const float*)d_in[4];
    const float* gat_bias = (const float*)d_in[5];
    const float* w_ih     = (const float*)d_in[6];
    const float* w_hh     = (const float*)d_in[7];
    const float* b_ih     = (const float*)d_in[8];
    const float* b_hh     = (const float*)d_in[9];
    const float* u_w1     = (const float*)d_in[10];
    const float* u_b1     = (const float*)d_in[11];
    const float* u_w2     = (const float*)d_in[12];
    const float* u_b2     = (const float*)d_in[13];

    float* out       = (float*)d_out;
    float* out_h     = out;                                   // 16384*64
    float* out_corr  = out + (size_t)N_NODES * HID;           // 16384*16384
    float* out_mu    = out_corr + (size_t)N_NODES * N_NODES;  // 16384
    float* out_sigma = out_mu + N_NODES;                      // 16384

    (void)in_sizes; (void)n_in; (void)out_size;

    k_detect<<<1, 1>>>(ei);
    k_init<<<512, 256>>>();
    k_gemm_h<<<dim3(FEAT / 64, N_NODES / 64), 256>>>(x, lin_w);
    k_attn<<<N_NODES / 8, 256>>>(att_src, att_dst);
    k_edge_z<<<(ET + 255) / 256, 256>>>(ei);
    k_edge_msg<<<(ET + 3) / 4, 256>>>(ei);
    k_gemm_xg<<<dim3(G4 / 64, N_NODES / 64), 256>>>(w_ih, gat_bias, b_ih, b_hh);
    k_lstm<<<1, 128>>>(w_hh, out_h);
    k_norm<<<N_NODES / 8, 256>>>(out_h);
    k_corr_sym<<<dim3(N_NODES / 64, N_NODES / 64), 256>>>(out_corr);
    k_mlp<<<N_NODES / 8, 256>>>(out_h, u_w1, u_b1, u_w2, u_b2, out_mu, out_sigma);
}